// round 10
// baseline (speedup 1.0000x reference)
#include <cuda_runtime.h>
#include <math.h>
#include <stdint.h>

#define B_  2
#define S_  2048
#define D_  1024
#define H_  16
#define HD_ 64
#define M_  (B_*S_)   // 4096
#define LOG2E 1.4426950408889634f

// Scratch (allocation-free rule)
__device__ float g_Q[B_*H_*S_*HD_];
__device__ float g_K[B_*H_*S_*HD_];
__device__ float g_V[B_*H_*HD_*S_];   // TRANSPOSED: [b,h,hd,s]
__device__ float g_A[B_*S_*D_];
__device__ float g_xc[M_*D_];         // tf32-rounded x
__device__ float g_wc[4*D_*D_];       // tf32-rounded Wq,Wk,Wv,Wo

__device__ __forceinline__ uint32_t f2tf(float x) {
    uint32_t r;
    asm("cvt.rna.tf32.f32 %0, %1;" : "=r"(r) : "f"(x));
    return r;
}

// D += A(16x8,row) * B(8x8,col)  tf32
__device__ __forceinline__ void mma8(float d[4], const uint32_t a[4], const uint32_t b[2]) {
    asm volatile(
        "mma.sync.aligned.m16n8k8.row.col.f32.tf32.tf32.f32 "
        "{%0,%1,%2,%3}, {%4,%5,%6,%7}, {%8,%9}, {%0,%1,%2,%3};\n"
        : "+f"(d[0]), "+f"(d[1]), "+f"(d[2]), "+f"(d[3])
        : "r"(a[0]), "r"(a[1]), "r"(a[2]), "r"(a[3]), "r"(b[0]), "r"(b[1]));
}

__device__ __forceinline__ void cpa16(uint32_t dst, const float* src) {
    asm volatile("cp.async.cg.shared.global [%0], [%1], 16;" :: "r"(dst), "l"(src));
}
__device__ __forceinline__ void cp_commit() { asm volatile("cp.async.commit_group;"); }
template<int N> __device__ __forceinline__ void cp_wait() {
    asm volatile("cp.async.wait_group %0;" :: "n"(N));
}

// ---------------------------------------------------------------------------
// Pre-round x and 4 weights to tf32 (rna)
// ---------------------------------------------------------------------------
__global__ __launch_bounds__(256) void precvt(const float* __restrict__ x,
                                              const float* __restrict__ Wq,
                                              const float* __restrict__ Wk,
                                              const float* __restrict__ Wv,
                                              const float* __restrict__ Wo)
{
    const int yy = blockIdx.y;
    const float* src; float* dst; int n4;
    if (yy == 0)      { src = x;  dst = g_xc;           n4 = M_*D_/4; }
    else if (yy == 1) { src = Wq; dst = g_wc;           n4 = D_*D_/4; }
    else if (yy == 2) { src = Wk; dst = g_wc + 1*D_*D_; n4 = D_*D_/4; }
    else if (yy == 3) { src = Wv; dst = g_wc + 2*D_*D_; n4 = D_*D_/4; }
    else              { src = Wo; dst = g_wc + 3*D_*D_; n4 = D_*D_/4; }
#pragma unroll
    for (int it = 0; it < 4; it++) {
        int i = (blockIdx.x * 256 + threadIdx.x) + it * 256 * gridDim.x;
        if (i < n4) {
            float4 v = ((const float4*)src)[i];
            ((uint4*)dst)[i] = make_uint4(f2tf(v.x), f2tf(v.y), f2tf(v.z), f2tf(v.w));
        }
    }
}

// ---------------------------------------------------------------------------
// tf32 GEMM: 128x256 CTA tile, 256 thr (8 warps as 2x4), warp tile 64x64,
// BK=32, cp.async double-buffered, float2 fragment loads (k-relabel).
// mma:LDS ratio = 2.0 -> tensor-pipe-dominant.
// ---------------------------------------------------------------------------
#define BM 128
#define BN 256
#define BK 32
#define SKG 40              // stride in floats -> conflict-free float2 frags
#define SB_OFF (2 * BM * SKG)                          // sB after both A bufs
#define GEMM_SMEM ((2 * BM * SKG + 2 * BN * SKG) * sizeof(float))  // 122,880 B

__device__ __forceinline__ void gemm_main(const float* __restrict__ A,
                                          const float* __restrict__ W,
                                          int m_base, int n_base,
                                          const float* sA, const float* sB,
                                          uint32_t sA_u, uint32_t sB_u,
                                          float acc[4][8][4])
{
    const int tid  = threadIdx.x;
    const int lane = tid & 31;
    const int warp = tid >> 5;
    const int g  = lane >> 2;
    const int t4 = lane & 3;
    const int wm = warp & 1;     // 2 m-quadrants of 64
    const int wn = warp >> 1;    // 4 n-quadrants of 64

    auto stage = [&](int buf, int k0) {
        // A: 128 rows x 8 16B-chunks = 1024
#pragma unroll
        for (int it = 0; it < 4; it++) {
            int id = tid + it * 256;
            int r  = id >> 3;
            int c4 = (id & 7) * 4;
            cpa16(sA_u + (uint32_t)((buf * BM + r) * SKG + c4) * 4u,
                  &A[(size_t)(m_base + r) * D_ + k0 + c4]);
        }
        // B: 256 rows x 8 = 2048
#pragma unroll
        for (int it = 0; it < 8; it++) {
            int id = tid + it * 256;
            int r  = id >> 3;
            int c4 = (id & 7) * 4;
            cpa16(sB_u + (uint32_t)((buf * BN + r) * SKG + c4) * 4u,
                  &W[(size_t)(n_base + r) * D_ + k0 + c4]);
        }
    };

    stage(0, 0);
    cp_commit();

#pragma unroll 2
    for (int ki = 0; ki < D_ / BK; ki++) {
        const int cur = ki & 1;
        if (ki + 1 < D_ / BK) {
            stage(cur ^ 1, (ki + 1) * BK);
            cp_commit();
            cp_wait<1>();
        } else {
            cp_wait<0>();
        }
        __syncthreads();

        const float* Ac = sA + cur * BM * SKG;
        const float* Bc = sB + cur * BN * SKG;
#pragma unroll
        for (int kk = 0; kk < BK; kk += 8) {
            uint32_t af[4][4];
#pragma unroll
            for (int ma = 0; ma < 4; ma++) {
                int row = wm * 64 + ma * 16;
                float2 lo = *(const float2*)&Ac[(row + g)     * SKG + kk + 2 * t4];
                float2 hi = *(const float2*)&Ac[(row + g + 8) * SKG + kk + 2 * t4];
                af[ma][0] = __float_as_uint(lo.x);
                af[ma][1] = __float_as_uint(hi.x);
                af[ma][2] = __float_as_uint(lo.y);
                af[ma][3] = __float_as_uint(hi.y);
            }
#pragma unroll
            for (int na = 0; na < 8; na++) {
                int col = wn * 64 + na * 8 + g;
                float2 bv = *(const float2*)&Bc[col * SKG + kk + 2 * t4];
                uint32_t bf[2] = { __float_as_uint(bv.x), __float_as_uint(bv.y) };
#pragma unroll
                for (int ma = 0; ma < 4; ma++)
                    mma8(acc[ma][na], af[ma], bf);
            }
        }
        __syncthreads();
    }
}

// Fused QKV. Q scaled by 0.125*log2e; V stored transposed [b,h,hd,s].
__global__ __launch_bounds__(256, 1) void qkv_gemm()
{
    extern __shared__ float sm[];
    const float* sA = sm;
    const float* sB = sm + SB_OFF;
    uint32_t sA_u = (uint32_t)__cvta_generic_to_shared(sm);
    uint32_t sB_u = (uint32_t)__cvta_generic_to_shared(sm + SB_OFF);

    const int wsel = blockIdx.y >> 2;
    const float* W = g_wc + (size_t)wsel * D_ * D_;
    float* Cout    = (wsel == 0) ? g_Q : (wsel == 1) ? g_K : g_V;
    const float scale = (wsel == 0) ? (0.125f * LOG2E) : 1.0f;
    const int m_base = blockIdx.x * BM;
    const int n_base = (blockIdx.y & 3) * BN;

    float acc[4][8][4];
#pragma unroll
    for (int ma = 0; ma < 4; ma++)
#pragma unroll
        for (int na = 0; na < 8; na++)
#pragma unroll
            for (int i = 0; i < 4; i++) acc[ma][na][i] = 0.f;

    gemm_main(g_xc, W, m_base, n_base, sA, sB, sA_u, sB_u, acc);

    const int lane = threadIdx.x & 31, warp = threadIdx.x >> 5;
    const int g = lane >> 2, t4 = lane & 3;
    const int wm = warp & 1, wn = warp >> 1;
#pragma unroll
    for (int ma = 0; ma < 4; ma++)
#pragma unroll
        for (int na = 0; na < 8; na++) {
            int m0 = m_base + wm * 64 + ma * 16 + g;
            int n0 = n_base + wn * 64 + na * 8 + 2 * t4;
#pragma unroll
            for (int i = 0; i < 4; i++) {
                int m = m0 + (i >> 1) * 8;
                int n = n0 + (i & 1);
                int b = m >> 11, s = m & 2047;
                int h = n >> 6, hd = n & 63;
                uint32_t bits = f2tf(acc[ma][na][i] * scale);
                size_t idx;
                if (wsel == 2)  // V transposed: [b,h,hd,s]
                    idx = ((size_t)(b * H_ + h) * HD_ + hd) * S_ + s;
                else
                    idx = ((size_t)(b * H_ + h) * S_ + s) * HD_ + hd;
                ((uint32_t*)Cout)[idx] = bits;
            }
        }
}

// Output projection: out = A @ Wo^T (fp32 output)
__global__ __launch_bounds__(256, 1) void out_gemm(float* __restrict__ out)
{
    extern __shared__ float sm[];
    const float* sA = sm;
    const float* sB = sm + SB_OFF;
    uint32_t sA_u = (uint32_t)__cvta_generic_to_shared(sm);
    uint32_t sB_u = (uint32_t)__cvta_generic_to_shared(sm + SB_OFF);

    const int m_base = blockIdx.x * BM;
    const int n_base = blockIdx.y * BN;

    float acc[4][8][4];
#pragma unroll
    for (int ma = 0; ma < 4; ma++)
#pragma unroll
        for (int na = 0; na < 8; na++)
#pragma unroll
            for (int i = 0; i < 4; i++) acc[ma][na][i] = 0.f;

    gemm_main(g_A, g_wc + 3 * D_ * D_, m_base, n_base, sA, sB, sA_u, sB_u, acc);

    const int lane = threadIdx.x & 31, warp = threadIdx.x >> 5;
    const int g = lane >> 2, t4 = lane & 3;
    const int wm = warp & 1, wn = warp >> 1;
#pragma unroll
    for (int ma = 0; ma < 4; ma++)
#pragma unroll
        for (int na = 0; na < 8; na++) {
            int m0 = m_base + wm * 64 + ma * 16 + g;
            int n0 = n_base + wn * 64 + na * 8 + 2 * t4;
#pragma unroll
            for (int i = 0; i < 4; i++) {
                int m = m0 + (i >> 1) * 8;
                int n = n0 + (i & 1);
                out[(size_t)m * D_ + n] = acc[ma][na][i];
            }
        }
}

// ---------------------------------------------------------------------------
// Flash attention (unchanged from round 9). CTA = (b,h,128-q-tile), 128 thr /
// 4 warps, warp = 32 rows. Double-buffered cp.async K/V. Transposed V.
// ---------------------------------------------------------------------------
#define FS 72
#define OFF_K (128 * FS)
#define OFF_V (OFF_K + 2 * 64 * FS)
#define FLASH_SMEM ((OFF_V + 2 * 64 * FS) * sizeof(float))

__global__ __launch_bounds__(128, 2) void flash_mma()
{
    extern __shared__ float fsm[];
    float (*Qs)[FS] = (float(*)[FS])(fsm);
    const uint32_t smem_base = (uint32_t)__cvta_generic_to_shared(fsm);

    const int t = (gridDim.x - 1) - blockIdx.x;   // heavy tiles first
    const int h = blockIdx.y;
    const int b = blockIdx.z;
    const int tid  = threadIdx.x;
    const int lane = tid & 31;
    const int w    = tid >> 5;
    const int g  = lane >> 2;
    const int t4 = lane & 3;

    const float* Qp  = g_Q + ((size_t)(b * H_ + h) * S_ + t * 128) * HD_;
    const float* Kp  = g_K + ((size_t)(b * H_ + h) * S_) * HD_;
    const float* Vtp = g_V + ((size_t)(b * H_ + h)) * HD_ * S_;   // [hd][s]

#pragma unroll
    for (int it = 0; it < 16; it++) {
        int f = tid + it * 128;
        int r = f >> 4, c = (f & 15) * 4;
        cpa16(smem_base + (uint32_t)(r * FS + c) * 4u, &Qp[(size_t)r * HD_ + c]);
    }
#pragma unroll
    for (int it = 0; it < 8; it++) {
        int f = tid + it * 128;
        int r = f >> 4, c = (f & 15) * 4;
        cpa16(smem_base + (uint32_t)(OFF_K + r * FS + c) * 4u, &Kp[(size_t)r * HD_ + c]);
        cpa16(smem_base + (uint32_t)(OFF_V + r * FS + c) * 4u, &Vtp[(size_t)r * S_ + c]);
    }
    cp_commit();

    const float slope2 = exp2f(-0.5f * (float)(h + 1)) * LOG2E;
    int qr[2][2];
#pragma unroll
    for (int rb = 0; rb < 2; rb++) {
        qr[rb][0] = t * 128 + w * 32 + rb * 16 + g;
        qr[rb][1] = qr[rb][0] + 8;
    }

    float o[2][8][4];
    float mr[2][2], lr[2][2];
#pragma unroll
    for (int rb = 0; rb < 2; rb++) {
        mr[rb][0] = mr[rb][1] = -INFINITY;
        lr[rb][0] = lr[rb][1] = 0.f;
#pragma unroll
        for (int da = 0; da < 8; da++)
#pragma unroll
            for (int i = 0; i < 4; i++) o[rb][da][i] = 0.f;
    }

    const int j_end = t * 128 + 64;
    for (int j0 = 0; j0 <= j_end; j0 += 64) {
        const int cur = (j0 >> 6) & 1;
        if (j0 + 64 <= j_end) {
            const int nb = cur ^ 1;
#pragma unroll
            for (int it = 0; it < 8; it++) {
                int f = tid + it * 128;
                int r = f >> 4, c = (f & 15) * 4;
                cpa16(smem_base + (uint32_t)(OFF_K + (nb * 64 + r) * FS + c) * 4u,
                      &Kp[(size_t)(j0 + 64 + r) * HD_ + c]);
                cpa16(smem_base + (uint32_t)(OFF_V + (nb * 64 + r) * FS + c) * 4u,
                      &Vtp[(size_t)r * S_ + j0 + 64 + c]);
            }
            cp_commit();
            cp_wait<1>();
        } else {
            cp_wait<0>();
        }
        __syncthreads();

        const float (*Kc)[FS] = (const float(*)[FS])(fsm + OFF_K) + cur * 64;
        const float (*Vc)[FS] = (const float(*)[FS])(fsm + OFF_V) + cur * 64;

        float s[2][8][4];
#pragma unroll
        for (int rb = 0; rb < 2; rb++)
#pragma unroll
            for (int na = 0; na < 8; na++)
#pragma unroll
                for (int i = 0; i < 4; i++) s[rb][na][i] = 0.f;

#pragma unroll
        for (int kk = 0; kk < 8; kk++) {
            uint32_t aq[2][4];
#pragma unroll
            for (int rb = 0; rb < 2; rb++) {
                int row = w * 32 + rb * 16 + g;
                float2 lo = *(const float2*)&Qs[row][kk * 8 + 2 * t4];
                float2 hi = *(const float2*)&Qs[row + 8][kk * 8 + 2 * t4];
                aq[rb][0] = __float_as_uint(lo.x);
                aq[rb][1] = __float_as_uint(hi.x);
                aq[rb][2] = __float_as_uint(lo.y);
                aq[rb][3] = __float_as_uint(hi.y);
            }
#pragma unroll
            for (int na = 0; na < 8; na++) {
                float2 bv = *(const float2*)&Kc[na * 8 + g][kk * 8 + 2 * t4];
                uint32_t bf[2] = { __float_as_uint(bv.x), __float_as_uint(bv.y) };
                mma8(s[0][na], aq[0], bf);
                mma8(s[1][na], aq[1], bf);
            }
        }

#pragma unroll
        for (int rb = 0; rb < 2; rb++) {
            const bool nm = (j0 + 63) > (t * 128 + w * 32 + rb * 16);
#pragma unroll
            for (int na = 0; na < 8; na++) {
                int jc = j0 + na * 8 + 2 * t4;
                s[rb][na][0] += slope2 * (float)(jc - qr[rb][0]);
                s[rb][na][1] += slope2 * (float)(jc + 1 - qr[rb][0]);
                s[rb][na][2] += slope2 * (float)(jc - qr[rb][1]);
                s[rb][na][3] += slope2 * (float)(jc + 1 - qr[rb][1]);
                if (nm) {
                    if (jc     > qr[rb][0]) s[rb][na][0] = -1e30f;
                    if (jc + 1 > qr[rb][0]) s[rb][na][1] = -1e30f;
                    if (jc     > qr[rb][1]) s[rb][na][2] = -1e30f;
                    if (jc + 1 > qr[rb][1]) s[rb][na][3] = -1e30f;
                }
            }
        }

#pragma unroll
        for (int rb = 0; rb < 2; rb++) {
            float mxA = -INFINITY, mxB = -INFINITY;
#pragma unroll
            for (int na = 0; na < 8; na++) {
                mxA = fmaxf(mxA, fmaxf(s[rb][na][0], s[rb][na][1]));
                mxB = fmaxf(mxB, fmaxf(s[rb][na][2], s[rb][na][3]));
            }
            mxA = fmaxf(mxA, __shfl_xor_sync(0xffffffffu, mxA, 1));
            mxA = fmaxf(mxA, __shfl_xor_sync(0xffffffffu, mxA, 2));
            mxB = fmaxf(mxB, __shfl_xor_sync(0xffffffffu, mxB, 1));
            mxB = fmaxf(mxB, __shfl_xor_sync(0xffffffffu, mxB, 2));

            float mnA = fmaxf(mr[rb][0], mxA), mnB = fmaxf(mr[rb][1], mxB);
            float aAl = exp2f(mr[rb][0] - mnA), aBl = exp2f(mr[rb][1] - mnB);
            mr[rb][0] = mnA; mr[rb][1] = mnB;

            float sumA = 0.f, sumB = 0.f;
#pragma unroll
            for (int na = 0; na < 8; na++) {
                s[rb][na][0] = exp2f(s[rb][na][0] - mnA);
                s[rb][na][1] = exp2f(s[rb][na][1] - mnA);
                s[rb][na][2] = exp2f(s[rb][na][2] - mnB);
                s[rb][na][3] = exp2f(s[rb][na][3] - mnB);
                sumA += s[rb][na][0] + s[rb][na][1];
                sumB += s[rb][na][2] + s[rb][na][3];
            }
            sumA += __shfl_xor_sync(0xffffffffu, sumA, 1);
            sumA += __shfl_xor_sync(0xffffffffu, sumA, 2);
            sumB += __shfl_xor_sync(0xffffffffu, sumB, 1);
            sumB += __shfl_xor_sync(0xffffffffu, sumB, 2);
            lr[rb][0] = lr[rb][0] * aAl + sumA;
            lr[rb][1] = lr[rb][1] * aBl + sumB;

#pragma unroll
            for (int da = 0; da < 8; da++) {
                o[rb][da][0] *= aAl; o[rb][da][1] *= aAl;
                o[rb][da][2] *= aBl; o[rb][da][3] *= aBl;
            }
        }

#pragma unroll
        for (int kk = 0; kk < 8; kk++) {
            uint32_t ap[2][4];
#pragma unroll
            for (int rb = 0; rb < 2; rb++) {
                ap[rb][0] = f2tf(s[rb][kk][0]);
                ap[rb][1] = f2tf(s[rb][kk][2]);
                ap[rb][2] = f2tf(s[rb][kk][1]);
                ap[rb][3] = f2tf(s[rb][kk][3]);
            }
#pragma unroll
            for (int da = 0; da < 8; da++) {
                float2 vv = *(const float2*)&Vc[da * 8 + g][kk * 8 + 2 * t4];
                uint32_t bf[2] = { __float_as_uint(vv.x), __float_as_uint(vv.y) };
                mma8(o[0][da], ap[0], bf);
                mma8(o[1][da], ap[1], bf);
            }
        }
        __syncthreads();
    }

    uint32_t* Aout = (uint32_t*)g_A;
#pragma unroll
    for (int rb = 0; rb < 2; rb++) {
        const float invA = 1.0f / lr[rb][0], invB = 1.0f / lr[rb][1];
#pragma unroll
        for (int da = 0; da < 8; da++) {
            int col = h * 64 + da * 8 + 2 * t4;
            size_t rA = ((size_t)b * S_ + qr[rb][0]) * D_ + col;
            size_t rB = ((size_t)b * S_ + qr[rb][1]) * D_ + col;
            Aout[rA]     = f2tf(o[rb][da][0] * invA);
            Aout[rA + 1] = f2tf(o[rb][da][1] * invA);
            Aout[rB]     = f2tf(o[rb][da][2] * invB);
            Aout[rB + 1] = f2tf(o[rb][da][3] * invB);
        }
    }
}

// ---------------------------------------------------------------------------
extern "C" void kernel_launch(void* const* d_in, const int* in_sizes, int n_in,
                              void* d_out, int out_size)
{
    const float* x  = (const float*)d_in[0];
    // d_in[1] = causal mask, applied analytically
    const float* Wq = (const float*)d_in[2];
    const float* Wk = (const float*)d_in[3];
    const float* Wv = (const float*)d_in[4];
    const float* Wo = (const float*)d_in[5];
    float* out = (float*)d_out;

    cudaFuncSetAttribute(qkv_gemm, cudaFuncAttributeMaxDynamicSharedMemorySize, (int)GEMM_SMEM);
    cudaFuncSetAttribute(out_gemm, cudaFuncAttributeMaxDynamicSharedMemorySize, (int)GEMM_SMEM);
    cudaFuncSetAttribute(flash_mma, cudaFuncAttributeMaxDynamicSharedMemorySize, (int)FLASH_SMEM);

    dim3 g0(1024, 5);
    precvt<<<g0, 256>>>(x, Wq, Wk, Wv, Wo);

    dim3 g1(M_ / BM, 12);                 // 3 weights x 4 n-tiles of 256
    qkv_gemm<<<g1, 256, GEMM_SMEM>>>();

    dim3 g2(S_ / 128, H_, B_);
    flash_mma<<<g2, 128, FLASH_SMEM>>>();

    dim3 g3(M_ / BM, D_ / BN);
    out_gemm<<<g3, 256, GEMM_SMEM>>>(out);
}

// round 12
// speedup vs baseline: 1.7156x; 1.7156x over previous
#include <cuda_runtime.h>
#include <cuda_fp16.h>
#include <math.h>
#include <stdint.h>

#define B_  2
#define S_  2048
#define D_  1024
#define H_  16
#define HD_ 64
#define M_  (B_*S_)   // 4096
#define LOG2E 1.4426950408889634f

// Scratch (allocation-free rule) — all fp16
__device__ __half g_Qh[B_*H_*S_*HD_];
__device__ __half g_Kh[B_*H_*S_*HD_];
__device__ __half g_Vh[B_*H_*HD_*S_];   // TRANSPOSED: [b,h,hd,s]
__device__ __half g_Ah[M_*D_];
__device__ __half g_xh[M_*D_];
__device__ __half g_wh[4*D_*D_];

__device__ __forceinline__ uint32_t h2u(__half2 h) { return *reinterpret_cast<uint32_t*>(&h); }

// D += A(16x16,row) * B(16x8,col)  fp16 inputs, fp32 accum
__device__ __forceinline__ void mma16(float d[4], const uint32_t a[4], const uint32_t b[2]) {
    asm volatile(
        "mma.sync.aligned.m16n8k16.row.col.f32.f16.f16.f32 "
        "{%0,%1,%2,%3}, {%4,%5,%6,%7}, {%8,%9}, {%0,%1,%2,%3};\n"
        : "+f"(d[0]), "+f"(d[1]), "+f"(d[2]), "+f"(d[3])
        : "r"(a[0]), "r"(a[1]), "r"(a[2]), "r"(a[3]), "r"(b[0]), "r"(b[1]));
}

__device__ __forceinline__ void cpa16(uint32_t dst, const void* src) {
    asm volatile("cp.async.cg.shared.global [%0], [%1], 16;" :: "r"(dst), "l"(src));
}
__device__ __forceinline__ void cp_commit() { asm volatile("cp.async.commit_group;"); }
template<int N> __device__ __forceinline__ void cp_wait() {
    asm volatile("cp.async.wait_group %0;" :: "n"(N));
}

// ---------------------------------------------------------------------------
// Pre-convert x and 4 weights to fp16 (rn). 8 floats -> 8 halves per thread-iter.
// ---------------------------------------------------------------------------
__global__ __launch_bounds__(256) void precvt(const float* __restrict__ x,
                                              const float* __restrict__ Wq,
                                              const float* __restrict__ Wk,
                                              const float* __restrict__ Wv,
                                              const float* __restrict__ Wo)
{
    const int yy = blockIdx.y;
    const float* src; __half* dst; int n8;
    if (yy == 0)      { src = x;  dst = g_xh;           n8 = M_*D_/8; }
    else if (yy == 1) { src = Wq; dst = g_wh;           n8 = D_*D_/8; }
    else if (yy == 2) { src = Wk; dst = g_wh + 1*D_*D_; n8 = D_*D_/8; }
    else if (yy == 3) { src = Wv; dst = g_wh + 2*D_*D_; n8 = D_*D_/8; }
    else              { src = Wo; dst = g_wh + 3*D_*D_; n8 = D_*D_/8; }
#pragma unroll
    for (int it = 0; it < 2; it++) {
        int i = (blockIdx.x * 256 + threadIdx.x) + it * 256 * gridDim.x;
        if (i < n8) {
            float4 v0 = ((const float4*)src)[2*i];
            float4 v1 = ((const float4*)src)[2*i + 1];
            uint4 u;
            u.x = h2u(__floats2half2_rn(v0.x, v0.y));
            u.y = h2u(__floats2half2_rn(v0.z, v0.w));
            u.z = h2u(__floats2half2_rn(v1.x, v1.y));
            u.w = h2u(__floats2half2_rn(v1.z, v1.w));
            ((uint4*)dst)[i] = u;
        }
    }
}

// ---------------------------------------------------------------------------
// fp16 GEMM: 128x128 CTA, 256 thr (8 warps 4x2), warp 32x64, BK=32 halves,
// cp.async double-buffered. Native m16n8k16 frags via LDS.32 (stride 144B:
// bank = 4g+t4, conflict-free).
// ---------------------------------------------------------------------------
#define BM 128
#define BN 128
#define BK 32
#define SKB 144                                   // bytes per 32-half row
#define GBUF (BM * SKB)                           // 18432 B per buffer
#define GEMM_SMEM (4 * GBUF)                      // A0,A1,B0,B1 = 73,728 B

__device__ __forceinline__ void gemm_main(const __half* __restrict__ A,
                                          const __half* __restrict__ W,
                                          int m_base, int n_base,
                                          const char* smemc, uint32_t sm_u,
                                          float acc[2][8][4])
{
    const int tid  = threadIdx.x;
    const int lane = tid & 31;
    const int warp = tid >> 5;
    const int g  = lane >> 2;
    const int t4 = lane & 3;
    const int wm = warp & 3;
    const int wn = warp >> 2;

    auto stage = [&](int buf, int k0) {
#pragma unroll
        for (int it = 0; it < 2; it++) {
            int id = tid + it * 256;      // 512 16B chunks per operand
            int r  = id >> 2;
            int c  = id & 3;
            cpa16(sm_u + (uint32_t)(buf * GBUF + r * SKB + c * 16),
                  A + (size_t)(m_base + r) * D_ + k0 + c * 8);
            cpa16(sm_u + (uint32_t)(2 * GBUF + buf * GBUF + r * SKB + c * 16),
                  W + (size_t)(n_base + r) * D_ + k0 + c * 8);
        }
    };

    stage(0, 0);
    cp_commit();

    for (int ki = 0; ki < D_ / BK; ki++) {
        const int cur = ki & 1;
        if (ki + 1 < D_ / BK) {
            stage(cur ^ 1, (ki + 1) * BK);
            cp_commit();
            cp_wait<1>();
        } else {
            cp_wait<0>();
        }
        __syncthreads();

        const char* Ac = smemc + cur * GBUF;
        const char* Bc = smemc + 2 * GBUF + cur * GBUF;
#pragma unroll
        for (int kk = 0; kk < 2; kk++) {       // two k16 groups per chunk
            uint32_t af[2][4];
#pragma unroll
            for (int ma = 0; ma < 2; ma++) {
                const char* rp = Ac + (wm * 32 + ma * 16 + g) * SKB + kk * 32 + 4 * t4;
                af[ma][0] = *(const uint32_t*)(rp);
                af[ma][1] = *(const uint32_t*)(rp + 8 * SKB);
                af[ma][2] = *(const uint32_t*)(rp + 16);
                af[ma][3] = *(const uint32_t*)(rp + 8 * SKB + 16);
            }
#pragma unroll
            for (int na = 0; na < 8; na++) {
                const char* cp = Bc + (wn * 64 + na * 8 + g) * SKB + kk * 32 + 4 * t4;
                uint32_t bf[2];
                bf[0] = *(const uint32_t*)(cp);
                bf[1] = *(const uint32_t*)(cp + 16);
                mma16(acc[0][na], af[0], bf);
                mma16(acc[1][na], af[1], bf);
            }
        }
        __syncthreads();
    }
}

// Fused QKV. Q scaled by 0.125*log2e; V stored transposed [b,h,hd,s].
__global__ __launch_bounds__(256, 2) void qkv_gemm()
{
    extern __shared__ __align__(16) char smc[];
    uint32_t sm_u = (uint32_t)__cvta_generic_to_shared(smc);

    const int wsel = blockIdx.y >> 3;
    const __half* W = g_wh + (size_t)wsel * D_ * D_;
    __half* Cout    = (wsel == 0) ? g_Qh : (wsel == 1) ? g_Kh : g_Vh;
    const float scale = (wsel == 0) ? (0.125f * LOG2E) : 1.0f;
    const int m_base = blockIdx.x * BM;
    const int n_base = (blockIdx.y & 7) * BN;

    float acc[2][8][4];
#pragma unroll
    for (int ma = 0; ma < 2; ma++)
#pragma unroll
        for (int na = 0; na < 8; na++)
#pragma unroll
            for (int i = 0; i < 4; i++) acc[ma][na][i] = 0.f;

    gemm_main(g_xh, W, m_base, n_base, smc, sm_u, acc);

    const int lane = threadIdx.x & 31, warp = threadIdx.x >> 5;
    const int g = lane >> 2, t4 = lane & 3;
    const int wm = warp & 3, wn = warp >> 2;
#pragma unroll
    for (int ma = 0; ma < 2; ma++)
#pragma unroll
        for (int na = 0; na < 8; na++) {
            int m0 = m_base + wm * 32 + ma * 16 + g;
            int n0 = n_base + wn * 64 + na * 8 + 2 * t4;
#pragma unroll
            for (int half_row = 0; half_row < 2; half_row++) {
                int m = m0 + half_row * 8;
                float v0 = acc[ma][na][half_row * 2 + 0] * scale;
                float v1 = acc[ma][na][half_row * 2 + 1] * scale;
                int b = m >> 11, s = m & 2047;
                int h = n0 >> 6, hd = n0 & 63;
                if (wsel == 2) {   // V transposed: [b,h,hd,s]
                    size_t base = ((size_t)(b * H_ + h) * HD_ + hd) * S_ + s;
                    g_Vh[base]      = __float2half_rn(v0);
                    g_Vh[base + S_] = __float2half_rn(v1);
                } else {
                    size_t idx = ((size_t)(b * H_ + h) * S_ + s) * HD_ + hd;
                    *(__half2*)&Cout[idx] = __floats2half2_rn(v0, v1);
                }
            }
        }
}

// Output projection: out = A @ Wo^T (fp32 output)
__global__ __launch_bounds__(256, 2) void out_gemm(float* __restrict__ out)
{
    extern __shared__ __align__(16) char smc[];
    uint32_t sm_u = (uint32_t)__cvta_generic_to_shared(smc);

    const int m_base = blockIdx.x * BM;
    const int n_base = blockIdx.y * BN;

    float acc[2][8][4];
#pragma unroll
    for (int ma = 0; ma < 2; ma++)
#pragma unroll
        for (int na = 0; na < 8; na++)
#pragma unroll
            for (int i = 0; i < 4; i++) acc[ma][na][i] = 0.f;

    gemm_main(g_Ah, g_wh + 3 * D_ * D_, m_base, n_base, smc, sm_u, acc);

    const int lane = threadIdx.x & 31, warp = threadIdx.x >> 5;
    const int g = lane >> 2, t4 = lane & 3;
    const int wm = warp & 3, wn = warp >> 2;
#pragma unroll
    for (int ma = 0; ma < 2; ma++)
#pragma unroll
        for (int na = 0; na < 8; na++) {
            int m0 = m_base + wm * 32 + ma * 16 + g;
            int n0 = n_base + wn * 64 + na * 8 + 2 * t4;
            *(float2*)&out[(size_t)m0 * D_ + n0]       = make_float2(acc[ma][na][0], acc[ma][na][1]);
            *(float2*)&out[(size_t)(m0 + 8) * D_ + n0] = make_float2(acc[ma][na][2], acc[ma][na][3]);
        }
}

// ---------------------------------------------------------------------------
// Flash attention, fp16 mma. CTA = (b,h,128-q-tile), 128 thr / 4 warps,
// warp = 32 q-rows (two 16-row blocks). Double-buffered cp.async K/V,
// V transposed. PV A-frags packed straight from softmax registers.
// smem (stride 144B/row): Qs 18432 + Ks 2x9216 + Vt 2x9216 = 55,296 B.
// ---------------------------------------------------------------------------
#define FSB 144
#define FOFF_K (128 * FSB)
#define FOFF_V (FOFF_K + 2 * 64 * FSB)
#define FLASH_SMEM (FOFF_V + 2 * 64 * FSB)   // 55,296 B

__global__ __launch_bounds__(128, 2) void flash_mma()
{
    extern __shared__ __align__(16) char fsc[];
    const uint32_t sm_u = (uint32_t)__cvta_generic_to_shared(fsc);

    const int t = (gridDim.x - 1) - blockIdx.x;   // heavy tiles first
    const int h = blockIdx.y;
    const int b = blockIdx.z;
    const int tid  = threadIdx.x;
    const int lane = tid & 31;
    const int w    = tid >> 5;
    const int g  = lane >> 2;
    const int t4 = lane & 3;

    const __half* Qp  = g_Qh + ((size_t)(b * H_ + h) * S_ + t * 128) * HD_;
    const __half* Kp  = g_Kh + ((size_t)(b * H_ + h) * S_) * HD_;
    const __half* Vtp = g_Vh + ((size_t)(b * H_ + h)) * HD_ * S_;   // [hd][s]

    // stage Q: 128 rows x 8 chunks = 1024, 128 thr -> 8 iters
#pragma unroll
    for (int it = 0; it < 8; it++) {
        int f = tid + it * 128;
        int r = f >> 3, c = (f & 7) * 16;
        cpa16(sm_u + (uint32_t)(r * FSB + c), Qp + (size_t)r * HD_ + c / 2);
    }
    // stage K0 / Vt0: 64 rows x 8 chunks = 512 each -> 4 iters
#pragma unroll
    for (int it = 0; it < 4; it++) {
        int f = tid + it * 128;
        int r = f >> 3, c = (f & 7) * 16;
        cpa16(sm_u + (uint32_t)(FOFF_K + r * FSB + c), Kp + (size_t)r * HD_ + c / 2);
        cpa16(sm_u + (uint32_t)(FOFF_V + r * FSB + c), Vtp + (size_t)r * S_ + c / 2);
    }
    cp_commit();

    const float slope2 = exp2f(-0.5f * (float)(h + 1)) * LOG2E;
    int qr[2][2];
#pragma unroll
    for (int rb = 0; rb < 2; rb++) {
        qr[rb][0] = t * 128 + w * 32 + rb * 16 + g;
        qr[rb][1] = qr[rb][0] + 8;
    }

    float o[2][8][4];
    float mr[2][2], lr[2][2];
#pragma unroll
    for (int rb = 0; rb < 2; rb++) {
        mr[rb][0] = mr[rb][1] = -INFINITY;
        lr[rb][0] = lr[rb][1] = 0.f;
#pragma unroll
        for (int da = 0; da < 8; da++)
#pragma unroll
            for (int i = 0; i < 4; i++) o[rb][da][i] = 0.f;
    }

    const int j_end = t * 128 + 64;
    for (int j0 = 0; j0 <= j_end; j0 += 64) {
        const int cur = (j0 >> 6) & 1;
        if (j0 + 64 <= j_end) {
            const int nb = cur ^ 1;
#pragma unroll
            for (int it = 0; it < 4; it++) {
                int f = tid + it * 128;
                int r = f >> 3, c = (f & 7) * 16;
                cpa16(sm_u + (uint32_t)(FOFF_K + (nb * 64 + r) * FSB + c),
                      Kp + (size_t)(j0 + 64 + r) * HD_ + c / 2);
                cpa16(sm_u + (uint32_t)(FOFF_V + (nb * 64 + r) * FSB + c),
                      Vtp + (size_t)r * S_ + j0 + 64 + c / 2);
            }
            cp_commit();
            cp_wait<1>();
        } else {
            cp_wait<0>();
        }
        __syncthreads();

        const char* Kc = fsc + FOFF_K + cur * 64 * FSB;
        const char* Vc = fsc + FOFF_V + cur * 64 * FSB;

        // S = Q @ K^T : 4 k16-groups over HD=64
        float s[2][8][4];
#pragma unroll
        for (int rb = 0; rb < 2; rb++)
#pragma unroll
            for (int na = 0; na < 8; na++)
#pragma unroll
                for (int i = 0; i < 4; i++) s[rb][na][i] = 0.f;

#pragma unroll
        for (int kk = 0; kk < 4; kk++) {
            uint32_t aq[2][4];
#pragma unroll
            for (int rb = 0; rb < 2; rb++) {
                const char* rp = fsc + (w * 32 + rb * 16 + g) * FSB + kk * 32 + 4 * t4;
                aq[rb][0] = *(const uint32_t*)(rp);
                aq[rb][1] = *(const uint32_t*)(rp + 8 * FSB);
                aq[rb][2] = *(const uint32_t*)(rp + 16);
                aq[rb][3] = *(const uint32_t*)(rp + 8 * FSB + 16);
            }
#pragma unroll
            for (int na = 0; na < 8; na++) {
                const char* cp = Kc + (na * 8 + g) * FSB + kk * 32 + 4 * t4;
                uint32_t bf[2];
                bf[0] = *(const uint32_t*)(cp);
                bf[1] = *(const uint32_t*)(cp + 16);
                mma16(s[0][na], aq[0], bf);
                mma16(s[1][na], aq[1], bf);
            }
        }

        // ALiBi (base-2) + causal, per row-block
#pragma unroll
        for (int rb = 0; rb < 2; rb++) {
            const bool nm = (j0 + 63) > (t * 128 + w * 32 + rb * 16);
#pragma unroll
            for (int na = 0; na < 8; na++) {
                int jc = j0 + na * 8 + 2 * t4;
                s[rb][na][0] += slope2 * (float)(jc - qr[rb][0]);
                s[rb][na][1] += slope2 * (float)(jc + 1 - qr[rb][0]);
                s[rb][na][2] += slope2 * (float)(jc - qr[rb][1]);
                s[rb][na][3] += slope2 * (float)(jc + 1 - qr[rb][1]);
                if (nm) {
                    if (jc     > qr[rb][0]) s[rb][na][0] = -1e30f;
                    if (jc + 1 > qr[rb][0]) s[rb][na][1] = -1e30f;
                    if (jc     > qr[rb][1]) s[rb][na][2] = -1e30f;
                    if (jc + 1 > qr[rb][1]) s[rb][na][3] = -1e30f;
                }
            }
        }

        // online softmax (base-2); reduce over t4 lanes
#pragma unroll
        for (int rb = 0; rb < 2; rb++) {
            float mxA = -INFINITY, mxB = -INFINITY;
#pragma unroll
            for (int na = 0; na < 8; na++) {
                mxA = fmaxf(mxA, fmaxf(s[rb][na][0], s[rb][na][1]));
                mxB = fmaxf(mxB, fmaxf(s[rb][na][2], s[rb][na][3]));
            }
            mxA = fmaxf(mxA, __shfl_xor_sync(0xffffffffu, mxA, 1));
            mxA = fmaxf(mxA, __shfl_xor_sync(0xffffffffu, mxA, 2));
            mxB = fmaxf(mxB, __shfl_xor_sync(0xffffffffu, mxB, 1));
            mxB = fmaxf(mxB, __shfl_xor_sync(0xffffffffu, mxB, 2));

            float mnA = fmaxf(mr[rb][0], mxA), mnB = fmaxf(mr[rb][1], mxB);
            float aAl = exp2f(mr[rb][0] - mnA), aBl = exp2f(mr[rb][1] - mnB);
            mr[rb][0] = mnA; mr[rb][1] = mnB;

            float sumA = 0.f, sumB = 0.f;
#pragma unroll
            for (int na = 0; na < 8; na++) {
                s[rb][na][0] = exp2f(s[rb][na][0] - mnA);
                s[rb][na][1] = exp2f(s[rb][na][1] - mnA);
                s[rb][na][2] = exp2f(s[rb][na][2] - mnB);
                s[rb][na][3] = exp2f(s[rb][na][3] - mnB);
                sumA += s[rb][na][0] + s[rb][na][1];
                sumB += s[rb][na][2] + s[rb][na][3];
            }
            sumA += __shfl_xor_sync(0xffffffffu, sumA, 1);
            sumA += __shfl_xor_sync(0xffffffffu, sumA, 2);
            sumB += __shfl_xor_sync(0xffffffffu, sumB, 1);
            sumB += __shfl_xor_sync(0xffffffffu, sumB, 2);
            lr[rb][0] = lr[rb][0] * aAl + sumA;
            lr[rb][1] = lr[rb][1] * aBl + sumB;

#pragma unroll
            for (int da = 0; da < 8; da++) {
                o[rb][da][0] *= aAl; o[rb][da][1] *= aAl;
                o[rb][da][2] *= aBl; o[rb][da][3] *= aBl;
            }
        }

        // O += P @ V : 4 k16-groups over the 64 keys. A-frags from s regs.
#pragma unroll
        for (int kk = 0; kk < 4; kk++) {
            uint32_t ap[2][4];
#pragma unroll
            for (int rb = 0; rb < 2; rb++) {
                ap[rb][0] = h2u(__floats2half2_rn(s[rb][2*kk][0],   s[rb][2*kk][1]));
                ap[rb][1] = h2u(__floats2half2_rn(s[rb][2*kk][2],   s[rb][2*kk][3]));
                ap[rb][2] = h2u(__floats2half2_rn(s[rb][2*kk+1][0], s[rb][2*kk+1][1]));
                ap[rb][3] = h2u(__floats2half2_rn(s[rb][2*kk+1][2], s[rb][2*kk+1][3]));
            }
#pragma unroll
            for (int da = 0; da < 8; da++) {
                const char* cp = Vc + (da * 8 + g) * FSB + kk * 32 + 4 * t4;
                uint32_t bf[2];
                bf[0] = *(const uint32_t*)(cp);
                bf[1] = *(const uint32_t*)(cp + 16);
                mma16(o[0][da], ap[0], bf);
                mma16(o[1][da], ap[1], bf);
            }
        }
        __syncthreads();
    }

    // normalize + write [B,S,D] as fp16 (input to out_gemm)
#pragma unroll
    for (int rb = 0; rb < 2; rb++) {
        const float invA = 1.0f / lr[rb][0], invB = 1.0f / lr[rb][1];
#pragma unroll
        for (int da = 0; da < 8; da++) {
            int col = h * 64 + da * 8 + 2 * t4;
            size_t rA = ((size_t)b * S_ + qr[rb][0]) * D_ + col;
            size_t rB = ((size_t)b * S_ + qr[rb][1]) * D_ + col;
            *(__half2*)&g_Ah[rA] = __floats2half2_rn(o[rb][da][0] * invA, o[rb][da][1] * invA);
            *(__half2*)&g_Ah[rB] = __floats2half2_rn(o[rb][da][2] * invB, o[rb][da][3] * invB);
        }
    }
}

// ---------------------------------------------------------------------------
extern "C" void kernel_launch(void* const* d_in, const int* in_sizes, int n_in,
                              void* d_out, int out_size)
{
    const float* x  = (const float*)d_in[0];
    // d_in[1] = causal mask, applied analytically
    const float* Wq = (const float*)d_in[2];
    const float* Wk = (const float*)d_in[3];
    const float* Wv = (const float*)d_in[4];
    const float* Wo = (const float*)d_in[5];
    float* out = (float*)d_out;

    cudaFuncSetAttribute(qkv_gemm, cudaFuncAttributeMaxDynamicSharedMemorySize, (int)GEMM_SMEM);
    cudaFuncSetAttribute(out_gemm, cudaFuncAttributeMaxDynamicSharedMemorySize, (int)GEMM_SMEM);
    cudaFuncSetAttribute(flash_mma, cudaFuncAttributeMaxDynamicSharedMemorySize, (int)FLASH_SMEM);

    dim3 g0(1024, 5);
    precvt<<<g0, 256>>>(x, Wq, Wk, Wv, Wo);

    dim3 g1(M_ / BM, 24);                 // 3 weights x 8 n-tiles
    qkv_gemm<<<g1, 256, GEMM_SMEM>>>();

    dim3 g2(S_ / 128, H_, B_);
    flash_mma<<<g2, 128, FLASH_SMEM>>>();

    dim3 g3(M_ / BM, D_ / BN);
    out_gemm<<<g3, 256, GEMM_SMEM>>>(out);
}